// round 1
// baseline (speedup 1.0000x reference)
#include <cuda_runtime.h>
#include <cuda_fp16.h>
#include <stdint.h>

#define M_DIM 2048
#define N_DIM 8192
#define K_DIM 8192

// Scratch: fp16 copies of x and dequantized W. Static device globals (no alloc).
__device__ __half g_A[(size_t)M_DIM * K_DIM];   // 33.5 MB
__device__ __half g_B[(size_t)N_DIM * K_DIM];   // 134 MB

// ---------------------------------------------------------------------------
// Kernel 1: x (fp32) -> fp16
// ---------------------------------------------------------------------------
__global__ void split_x_kernel(const float* __restrict__ x) {
    size_t i = ((size_t)blockIdx.x * blockDim.x + threadIdx.x) * 4;
    float4 v = *reinterpret_cast<const float4*>(x + i);
    __half2 h0 = __floats2half2_rn(v.x, v.y);
    __half2 h1 = __floats2half2_rn(v.z, v.w);
    uint2 out;
    out.x = *reinterpret_cast<uint32_t*>(&h0);
    out.y = *reinterpret_cast<uint32_t*>(&h1);
    *reinterpret_cast<uint2*>(&g_A[i]) = out;
}

// ---------------------------------------------------------------------------
// Kernel 2: dequantize packed 3-bit indices -> fp16 W
// One thread per group of 8 weights (3 packed bytes, stored one byte per int32).
// Block b (128 weights) uses codebook[b*8 .. b*8+7]; 16 groups per block.
// ---------------------------------------------------------------------------
__global__ void dequant_kernel(const int* __restrict__ p,
                               const float* __restrict__ cb) {
    int G = blockIdx.x * blockDim.x + threadIdx.x;      // 0 .. 8388607
    int base = G * 3;
    unsigned bits = (unsigned)p[base]
                  | ((unsigned)p[base + 1] << 8)
                  | ((unsigned)p[base + 2] << 16);
    const float* c = cb + (size_t)(G >> 4) * 8;
    __half h[8];
#pragma unroll
    for (int j = 0; j < 8; j++) {
        int idx = (bits >> (3 * j)) & 7;
        h[j] = __float2half_rn(__ldg(c + idx));
    }
    size_t e = (size_t)G * 8;   // flat index into W (row-major N x K)
    *reinterpret_cast<uint4*>(&g_B[e]) = *reinterpret_cast<const uint4*>(h);
}

// ---------------------------------------------------------------------------
// Kernel 3: y[M,N] = A[M,K] * B[N,K]^T, fp16 inputs, fp32 accumulate.
// mma.sync.m16n8k16, BM=BN=128, BK=32, 8 warps (2x4), cp.async double buffer.
// ---------------------------------------------------------------------------
#define BM 128
#define BN 128
#define BK 32
#define PAD 8

__device__ __forceinline__ void mma16816(float* c, const uint32_t* a, const uint32_t* b) {
    asm volatile(
        "mma.sync.aligned.m16n8k16.row.col.f32.f16.f16.f32 "
        "{%0,%1,%2,%3}, {%4,%5,%6,%7}, {%8,%9}, {%0,%1,%2,%3};\n"
        : "+f"(c[0]), "+f"(c[1]), "+f"(c[2]), "+f"(c[3])
        : "r"(a[0]), "r"(a[1]), "r"(a[2]), "r"(a[3]),
          "r"(b[0]), "r"(b[1]));
}

__global__ void __launch_bounds__(256, 1) gemm_kernel(float* __restrict__ y) {
    __shared__ __half As[2][BM][BK + PAD];
    __shared__ __half Bs[2][BN][BK + PAD];

    const int bm = blockIdx.x * BM;   // grid.x = 16 (m tiles) -> wave shares B stripe
    const int bn = blockIdx.y * BN;   // grid.y = 64 (n tiles)
    const int t = threadIdx.x;
    const int lrow = t >> 2;          // 0..63
    const int lcol = (t & 3) * 8;     // 0,8,16,24 (halfs; 16B chunks)

    const int w = t >> 5;
    const int l = t & 31;
    const int wm = (w >> 2) * 64;     // warp m offset within tile
    const int wn = (w & 3) * 32;      // warp n offset within tile

    auto loadTile = [&](int buf, int k0) {
#pragma unroll
        for (int h = 0; h < 2; h++) {
            int row = lrow + h * 64;
            const __half* gA = &g_A[(size_t)(bm + row) * K_DIM + k0 + lcol];
            uint32_t sa = (uint32_t)__cvta_generic_to_shared(&As[buf][row][lcol]);
            asm volatile("cp.async.cg.shared.global [%0], [%1], 16;\n"
                         :: "r"(sa), "l"(gA));
            const __half* gB = &g_B[(size_t)(bn + row) * K_DIM + k0 + lcol];
            uint32_t sb = (uint32_t)__cvta_generic_to_shared(&Bs[buf][row][lcol]);
            asm volatile("cp.async.cg.shared.global [%0], [%1], 16;\n"
                         :: "r"(sb), "l"(gB));
        }
        asm volatile("cp.async.commit_group;\n");
    };

    float acc[4][4][4];
#pragma unroll
    for (int i = 0; i < 4; i++)
#pragma unroll
        for (int j = 0; j < 4; j++)
#pragma unroll
            for (int r = 0; r < 4; r++) acc[i][j][r] = 0.0f;

    loadTile(0, 0);

    const int nIt = K_DIM / BK;   // 256
    int buf = 0;
    for (int it = 0; it < nIt; it++) {
        asm volatile("cp.async.wait_group 0;\n");
        __syncthreads();
        if (it + 1 < nIt) loadTile(buf ^ 1, (it + 1) * BK);

#pragma unroll
        for (int kk = 0; kk < BK; kk += 16) {
            uint32_t ra[4][4];
            uint32_t rb[4][2];
            const int ccol = kk + (l & 3) * 2;
#pragma unroll
            for (int i = 0; i < 4; i++) {
                int r0 = wm + i * 16 + (l >> 2);
                ra[i][0] = *reinterpret_cast<const uint32_t*>(&As[buf][r0][ccol]);
                ra[i][1] = *reinterpret_cast<const uint32_t*>(&As[buf][r0 + 8][ccol]);
                ra[i][2] = *reinterpret_cast<const uint32_t*>(&As[buf][r0][ccol + 8]);
                ra[i][3] = *reinterpret_cast<const uint32_t*>(&As[buf][r0 + 8][ccol + 8]);
            }
#pragma unroll
            for (int j = 0; j < 4; j++) {
                int n0 = wn + j * 8 + (l >> 2);
                rb[j][0] = *reinterpret_cast<const uint32_t*>(&Bs[buf][n0][ccol]);
                rb[j][1] = *reinterpret_cast<const uint32_t*>(&Bs[buf][n0][ccol + 8]);
            }
#pragma unroll
            for (int i = 0; i < 4; i++)
#pragma unroll
                for (int j = 0; j < 4; j++)
                    mma16816(acc[i][j], ra[i], rb[j]);
        }
        __syncthreads();
        buf ^= 1;
    }

    // Epilogue: fp32 output, float2 stores.
#pragma unroll
    for (int i = 0; i < 4; i++) {
#pragma unroll
        for (int j = 0; j < 4; j++) {
            int row = bm + wm + i * 16 + (l >> 2);
            int col = bn + wn + j * 8 + (l & 3) * 2;
            *reinterpret_cast<float2*>(&y[(size_t)row * N_DIM + col]) =
                make_float2(acc[i][j][0], acc[i][j][1]);
            *reinterpret_cast<float2*>(&y[(size_t)(row + 8) * N_DIM + col]) =
                make_float2(acc[i][j][2], acc[i][j][3]);
        }
    }
}

// ---------------------------------------------------------------------------
extern "C" void kernel_launch(void* const* d_in, const int* in_sizes, int n_in,
                              void* d_out, int out_size) {
    const float* x  = (const float*)d_in[0];          // (2048, 8192) fp32
    const int*   p  = (const int*)d_in[1];            // 25165824 bytes-as-int32
    const float* cb = (const float*)d_in[2];          // (524288, 8) fp32
    float* y = (float*)d_out;                         // (2048, 8192) fp32

    // x -> fp16
    split_x_kernel<<<(M_DIM * (size_t)K_DIM / 4) / 256, 256>>>(x);
    // W dequant -> fp16
    dequant_kernel<<<((size_t)N_DIM * K_DIM / 8) / 256, 256>>>(p, cb);
    // GEMM
    dim3 grid(M_DIM / BM, N_DIM / BN);
    gemm_kernel<<<grid, 256>>>(y);
}

// round 3
// speedup vs baseline: 1.6817x; 1.6817x over previous
#include <cuda_runtime.h>
#include <cuda_fp16.h>
#include <stdint.h>

#define M_DIM 2048
#define N_DIM 8192
#define K_DIM 8192

// Scratch (static device globals, no alloc).
__device__ __align__(128) __half g_A[(size_t)M_DIM * K_DIM];   // 33.5 MB
__device__ __align__(128) __half g_B[(size_t)N_DIM * K_DIM];   // 134 MB

// ---------------------------------------------------------------------------
// Kernel 1: x (fp32) -> fp16
// ---------------------------------------------------------------------------
__global__ void split_x_kernel(const float* __restrict__ x) {
    size_t i = ((size_t)blockIdx.x * blockDim.x + threadIdx.x) * 4;
    float4 v = *reinterpret_cast<const float4*>(x + i);
    __half2 h0 = __floats2half2_rn(v.x, v.y);
    __half2 h1 = __floats2half2_rn(v.z, v.w);
    uint2 out;
    out.x = *reinterpret_cast<uint32_t*>(&h0);
    out.y = *reinterpret_cast<uint32_t*>(&h1);
    *reinterpret_cast<uint2*>(&g_A[i]) = out;
}

// ---------------------------------------------------------------------------
// Kernel 2: dequantize packed 3-bit indices -> fp16 W
// ---------------------------------------------------------------------------
__global__ void dequant_kernel(const int* __restrict__ p,
                               const float* __restrict__ cb) {
    int G = blockIdx.x * blockDim.x + threadIdx.x;      // 0 .. 8388607
    int base = G * 3;
    unsigned bits = (unsigned)p[base]
                  | ((unsigned)p[base + 1] << 8)
                  | ((unsigned)p[base + 2] << 16);
    const float* c = cb + (size_t)(G >> 4) * 8;
    __half h[8];
#pragma unroll
    for (int j = 0; j < 8; j++) {
        int idx = (bits >> (3 * j)) & 7;
        h[j] = __float2half_rn(__ldg(c + idx));
    }
    size_t e = (size_t)G * 8;
    *reinterpret_cast<uint4*>(&g_B[e]) = *reinterpret_cast<const uint4*>(h);
}

// ---------------------------------------------------------------------------
// Kernel 3: GEMM  y[M,N] = A[M,K] * B[N,K]^T   (fp16 in, fp32 acc)
// BM=128 BN=256 BK=64, 8 warps (2x4) -> warp tile 64x64.
// ldmatrix.x4 + XOR-swizzled 128B rows, 4-stage cp.async pipeline.
// ---------------------------------------------------------------------------
#define BM 128
#define BN 256
#define BK 64
#define NSTAGE 4
#define NITER (K_DIM / BK)              // 128
#define A_BYTES (BM * BK * 2)           // 16384
#define B_BYTES (BN * BK * 2)           // 32768
#define STAGE_BYTES (A_BYTES + B_BYTES) // 49152
#define GEMM_SMEM (NSTAGE * STAGE_BYTES) // 196608

__device__ __forceinline__ uint32_t smem_u32(const void* p) {
    uint32_t a;
    asm("{ .reg .u64 t; cvta.to.shared.u64 t, %1; cvt.u32.u64 %0, t; }"
        : "=r"(a) : "l"(p));
    return a;
}

// row of 64 halves = 128B = 8 chunks of 16B; chunk swizzle: c ^= (row & 7)
__device__ __forceinline__ uint32_t swz(uint32_t base, int row, int chunk) {
    return base + row * 128 + (((chunk ^ row) & 7) << 4);
}

__device__ __forceinline__ void cp16(uint32_t dst, const void* src) {
    asm volatile("cp.async.cg.shared.global [%0], [%1], 16;\n"
                 :: "r"(dst), "l"(src));
}

__device__ __forceinline__ void ldsm4(uint32_t* r, uint32_t addr) {
    asm volatile("ldmatrix.sync.aligned.m8n8.x4.shared.b16 {%0,%1,%2,%3}, [%4];"
                 : "=r"(r[0]), "=r"(r[1]), "=r"(r[2]), "=r"(r[3]) : "r"(addr));
}

__device__ __forceinline__ void mma16816(float* c, const uint32_t* a,
                                         const uint32_t* b) {
    asm volatile(
        "mma.sync.aligned.m16n8k16.row.col.f32.f16.f16.f32 "
        "{%0,%1,%2,%3}, {%4,%5,%6,%7}, {%8,%9}, {%0,%1,%2,%3};\n"
        : "+f"(c[0]), "+f"(c[1]), "+f"(c[2]), "+f"(c[3])
        : "r"(a[0]), "r"(a[1]), "r"(a[2]), "r"(a[3]), "r"(b[0]), "r"(b[1]));
}

__device__ __forceinline__ void load_stage(uint32_t sb, int tid, int bm, int bn,
                                           int buf, int chunk) {
    const int k0 = chunk * BK;
    const uint32_t abase = sb + buf * STAGE_BYTES;
    const uint32_t bbase = abase + A_BYTES;
#pragma unroll
    for (int i = 0; i < 4; i++) {                       // A: 128 rows x 8 chunks
        int c = tid + i * 256;
        int row = c >> 3, ch = c & 7;
        cp16(swz(abase, row, ch),
             g_A + (size_t)(bm + row) * K_DIM + k0 + ch * 8);
    }
#pragma unroll
    for (int i = 0; i < 8; i++) {                       // B: 256 rows x 8 chunks
        int c = tid + i * 256;
        int row = c >> 3, ch = c & 7;
        cp16(swz(bbase, row, ch),
             g_B + (size_t)(bn + row) * K_DIM + k0 + ch * 8);
    }
    asm volatile("cp.async.commit_group;" ::: "memory");
}

__global__ void __launch_bounds__(256, 1) gemm_kernel(float* __restrict__ y) {
    extern __shared__ char smem[];
    const uint32_t sb = smem_u32(smem);
    const int tid = threadIdx.x;
    const int w = tid >> 5, lane = tid & 31;
    const int wm = (w & 1) * 64;          // warp m offset (2 warps in M)
    const int wn = (w >> 1) * 64;         // warp n offset (4 warps in N)
    const int bm = blockIdx.x * BM;       // 16 M tiles (fastest -> share B stripe)
    const int bn = blockIdx.y * BN;       // 32 N stripes

    float acc[4][8][4];
#pragma unroll
    for (int i = 0; i < 4; i++)
#pragma unroll
        for (int j = 0; j < 8; j++)
#pragma unroll
            for (int r = 0; r < 4; r++) acc[i][j][r] = 0.0f;

    // Prologue: fill NSTAGE-1 stages
#pragma unroll
    for (int s = 0; s < NSTAGE - 1; s++)
        load_stage(sb, tid, bm, bn, s, s);

    for (int it = 0; it < NITER; it++) {
        if (it < NITER - (NSTAGE - 1))
            asm volatile("cp.async.wait_group %0;" :: "n"(NSTAGE - 2) : "memory");
        else
            asm volatile("cp.async.wait_group 0;" ::: "memory");
        __syncthreads();

        const int j = it + NSTAGE - 1;
        if (j < NITER) load_stage(sb, tid, bm, bn, j & (NSTAGE - 1), j);

        const int buf = it & (NSTAGE - 1);
        const uint32_t abase = sb + buf * STAGE_BYTES;
        const uint32_t bbase = abase + A_BYTES;

#pragma unroll
        for (int kk = 0; kk < 4; kk++) {          // 4 k-steps of 16
            uint32_t ra[4][4], rb[4][4];
            // A: 4 m16 tiles; lane L -> row wm+mi*16+(L&15), chunk kk*2+(L>>4)
#pragma unroll
            for (int mi = 0; mi < 4; mi++) {
                int row = wm + mi * 16 + (lane & 15);
                int ch = kk * 2 + (lane >> 4);
                ldsm4(ra[mi], swz(abase, row, ch));
            }
            // B: 4 pairs of n8 tiles; lane L -> row wn+np*16+(L&7)+((L>>4)<<3),
            //    chunk kk*2+((L>>3)&1)
#pragma unroll
            for (int np = 0; np < 4; np++) {
                int row = wn + np * 16 + (lane & 7) + ((lane >> 4) << 3);
                int ch = kk * 2 + ((lane >> 3) & 1);
                ldsm4(rb[np], swz(bbase, row, ch));
            }
#pragma unroll
            for (int mi = 0; mi < 4; mi++)
#pragma unroll
                for (int ni = 0; ni < 8; ni++)
                    mma16816(acc[mi][ni], ra[mi], &rb[ni >> 1][(ni & 1) * 2]);
        }
    }

    // Epilogue: direct fp32 stores
#pragma unroll
    for (int mi = 0; mi < 4; mi++) {
#pragma unroll
        for (int ni = 0; ni < 8; ni++) {
            int row = bm + wm + mi * 16 + (lane >> 2);
            int col = bn + wn + ni * 8 + (lane & 3) * 2;
            *reinterpret_cast<float2*>(&y[(size_t)row * N_DIM + col]) =
                make_float2(acc[mi][ni][0], acc[mi][ni][1]);
            *reinterpret_cast<float2*>(&y[(size_t)(row + 8) * N_DIM + col]) =
                make_float2(acc[mi][ni][2], acc[mi][ni][3]);
        }
    }
}

// ---------------------------------------------------------------------------
extern "C" void kernel_launch(void* const* d_in, const int* in_sizes, int n_in,
                              void* d_out, int out_size) {
    const float* x  = (const float*)d_in[0];
    const int*   p  = (const int*)d_in[1];
    const float* cb = (const float*)d_in[2];
    float* y = (float*)d_out;

    split_x_kernel<<<(M_DIM * (size_t)K_DIM / 4) / 256, 256>>>(x);
    dequant_kernel<<<((size_t)N_DIM * K_DIM / 8) / 256, 256>>>(p, cb);

    cudaFuncSetAttribute(gemm_kernel,
                         cudaFuncAttributeMaxDynamicSharedMemorySize, GEMM_SMEM);
    dim3 grid(M_DIM / BM, N_DIM / BN);   // 16 x 32
    gemm_kernel<<<grid, 256, GEMM_SMEM>>>(y);
}

// round 4
// speedup vs baseline: 2.0004x; 1.1895x over previous
#include <cuda_runtime.h>
#include <cuda_fp16.h>
#include <stdint.h>

#define M_DIM 2048
#define N_DIM 8192
#define K_DIM 8192

__device__ __align__(128) __half g_A[(size_t)M_DIM * K_DIM];   // 33.5 MB
__device__ __align__(128) __half g_B[(size_t)N_DIM * K_DIM];   // 134 MB

// ---------------------------------------------------------------------------
// Kernel 1: x (fp32) -> fp16
// ---------------------------------------------------------------------------
__global__ void split_x_kernel(const float* __restrict__ x) {
    size_t i = ((size_t)blockIdx.x * blockDim.x + threadIdx.x) * 4;
    float4 v = *reinterpret_cast<const float4*>(x + i);
    __half2 h0 = __floats2half2_rn(v.x, v.y);
    __half2 h1 = __floats2half2_rn(v.z, v.w);
    uint2 out;
    out.x = *reinterpret_cast<uint32_t*>(&h0);
    out.y = *reinterpret_cast<uint32_t*>(&h1);
    *reinterpret_cast<uint2*>(&g_A[i]) = out;
}

// ---------------------------------------------------------------------------
// Kernel 2: dequant. 4 groups (32 weights) per thread, int4 packed loads,
// codebook as fp16 table in 2 u64 regs, u64-shift select (no gathers).
// ---------------------------------------------------------------------------
__global__ void dequant_kernel(const int* __restrict__ p,
                               const float* __restrict__ cb) {
    int t = blockIdx.x * blockDim.x + threadIdx.x;      // 0 .. 2097151
    const int4* p4 = reinterpret_cast<const int4*>(p) + (size_t)t * 3;
    int4 pa = p4[0], pb = p4[1], pc = p4[2];
    int by[12] = {pa.x, pa.y, pa.z, pa.w, pb.x, pb.y, pb.z, pb.w,
                  pc.x, pc.y, pc.z, pc.w};

    const float4* c4 = reinterpret_cast<const float4*>(cb) + (size_t)(t >> 2) * 2;
    float4 f0 = __ldg(c4), f1 = __ldg(c4 + 1);
    uint64_t t0 = (uint64_t)__half_as_ushort(__float2half_rn(f0.x))
                | ((uint64_t)__half_as_ushort(__float2half_rn(f0.y)) << 16)
                | ((uint64_t)__half_as_ushort(__float2half_rn(f0.z)) << 32)
                | ((uint64_t)__half_as_ushort(__float2half_rn(f0.w)) << 48);
    uint64_t t1 = (uint64_t)__half_as_ushort(__float2half_rn(f1.x))
                | ((uint64_t)__half_as_ushort(__float2half_rn(f1.y)) << 16)
                | ((uint64_t)__half_as_ushort(__float2half_rn(f1.z)) << 32)
                | ((uint64_t)__half_as_ushort(__float2half_rn(f1.w)) << 48);

    uint4* dst = reinterpret_cast<uint4*>(g_B + (size_t)t * 32);
#pragma unroll
    for (int g = 0; g < 4; g++) {
        unsigned bits = (unsigned)by[3 * g] | ((unsigned)by[3 * g + 1] << 8)
                      | ((unsigned)by[3 * g + 2] << 16);
        uint32_t hv[8];
#pragma unroll
        for (int j = 0; j < 8; j++) {
            int idx = (bits >> (3 * j)) & 7;
            uint64_t tab = (idx & 4) ? t1 : t0;
            hv[j] = (uint32_t)(tab >> ((idx & 3) << 4)) & 0xFFFFu;
        }
        uint4 o;
        o.x = hv[0] | (hv[1] << 16);
        o.y = hv[2] | (hv[3] << 16);
        o.z = hv[4] | (hv[5] << 16);
        o.w = hv[6] | (hv[7] << 16);
        dst[g] = o;
    }
}

// ---------------------------------------------------------------------------
// Kernel 3: GEMM  y = A * B^T.  BM=BN=128, BK=64, 4 warps (2x2), warp 64x64,
// 3-stage cp.async, occ 2, ldmatrix.x4 + XOR swizzle, double-buffered frags.
// ---------------------------------------------------------------------------
#define BM 128
#define BN 128
#define BK 64
#define NSTAGE 3
#define NITER (K_DIM / BK)               // 128
#define A_BYTES (BM * BK * 2)            // 16384
#define B_BYTES (BN * BK * 2)            // 16384
#define STAGE_BYTES (A_BYTES + B_BYTES)  // 32768
#define GEMM_SMEM (NSTAGE * STAGE_BYTES) // 98304
#define GTHREADS 128

__device__ __forceinline__ uint32_t smem_u32(const void* p) {
    uint32_t a;
    asm("{ .reg .u64 t; cvta.to.shared.u64 t, %1; cvt.u32.u64 %0, t; }"
        : "=r"(a) : "l"(p));
    return a;
}

__device__ __forceinline__ uint32_t swz(uint32_t base, int row, int chunk) {
    return base + row * 128 + (((chunk ^ row) & 7) << 4);
}

__device__ __forceinline__ void cp16(uint32_t dst, const void* src) {
    asm volatile("cp.async.cg.shared.global [%0], [%1], 16;\n"
                 :: "r"(dst), "l"(src));
}

__device__ __forceinline__ void ldsm4(uint32_t* r, uint32_t addr) {
    asm volatile("ldmatrix.sync.aligned.m8n8.x4.shared.b16 {%0,%1,%2,%3}, [%4];"
                 : "=r"(r[0]), "=r"(r[1]), "=r"(r[2]), "=r"(r[3]) : "r"(addr));
}

__device__ __forceinline__ void mma16816(float* c, const uint32_t* a,
                                         const uint32_t* b) {
    asm volatile(
        "mma.sync.aligned.m16n8k16.row.col.f32.f16.f16.f32 "
        "{%0,%1,%2,%3}, {%4,%5,%6,%7}, {%8,%9}, {%0,%1,%2,%3};\n"
        : "+f"(c[0]), "+f"(c[1]), "+f"(c[2]), "+f"(c[3])
        : "r"(a[0]), "r"(a[1]), "r"(a[2]), "r"(a[3]), "r"(b[0]), "r"(b[1]));
}

__device__ __forceinline__ void load_stage(uint32_t sb, int tid, int bm, int bn,
                                           int buf, int chunk) {
    const int k0 = chunk * BK;
    const uint32_t abase = sb + buf * STAGE_BYTES;
    const uint32_t bbase = abase + A_BYTES;
#pragma unroll
    for (int i = 0; i < 8; i++) {                       // A: 128 rows x 8 chunks
        int c = tid + i * GTHREADS;
        int row = c >> 3, ch = c & 7;
        cp16(swz(abase, row, ch),
             g_A + (size_t)(bm + row) * K_DIM + k0 + ch * 8);
    }
#pragma unroll
    for (int i = 0; i < 8; i++) {                       // B: 128 rows x 8 chunks
        int c = tid + i * GTHREADS;
        int row = c >> 3, ch = c & 7;
        cp16(swz(bbase, row, ch),
             g_B + (size_t)(bn + row) * K_DIM + k0 + ch * 8);
    }
    asm volatile("cp.async.commit_group;" ::: "memory");
}

__global__ void __launch_bounds__(GTHREADS, 2) gemm_kernel(float* __restrict__ y) {
    extern __shared__ char smem[];
    const uint32_t sb = smem_u32(smem);
    const int tid = threadIdx.x;
    const int w = tid >> 5, lane = tid & 31;
    const int wm = (w & 1) * 64;
    const int wn = (w >> 1) * 64;
    const int bm = blockIdx.x * BM;      // 16 M tiles (fastest)
    const int bn = blockIdx.y * BN;      // 64 N stripes

    float acc[4][8][4];
#pragma unroll
    for (int i = 0; i < 4; i++)
#pragma unroll
        for (int j = 0; j < 8; j++)
#pragma unroll
            for (int r = 0; r < 4; r++) acc[i][j][r] = 0.0f;

#pragma unroll
    for (int s = 0; s < NSTAGE - 1; s++)
        load_stage(sb, tid, bm, bn, s, s);

    uint32_t ra[2][4][4], rb[2][4][4];

    // fragment-load helper (kk = k-step 0..3, pb = parity buffer)
    auto ldfrag = [&](uint32_t abase, uint32_t bbase, int kk, int pb) {
#pragma unroll
        for (int mi = 0; mi < 4; mi++) {
            int row = wm + mi * 16 + (lane & 15);
            int ch = kk * 2 + (lane >> 4);
            ldsm4(ra[pb][mi], swz(abase, row, ch));
        }
#pragma unroll
        for (int np = 0; np < 4; np++) {
            int row = wn + np * 16 + (lane & 7) + ((lane >> 4) << 3);
            int ch = kk * 2 + ((lane >> 3) & 1);
            ldsm4(rb[pb][np], swz(bbase, row, ch));
        }
    };

    for (int it = 0; it < NITER; it++) {
        if (it < NITER - (NSTAGE - 1))
            asm volatile("cp.async.wait_group %0;" :: "n"(NSTAGE - 2) : "memory");
        else
            asm volatile("cp.async.wait_group 0;" ::: "memory");
        __syncthreads();

        const int j = it + NSTAGE - 1;
        if (j < NITER) {
            int jb = j % NSTAGE;
            load_stage(sb, tid, bm, bn, jb, j);
        }

        const int buf = it % NSTAGE;
        const uint32_t abase = sb + buf * STAGE_BYTES;
        const uint32_t bbase = abase + A_BYTES;

        ldfrag(abase, bbase, 0, 0);
#pragma unroll
        for (int kk = 0; kk < 4; kk++) {
            if (kk < 3) ldfrag(abase, bbase, kk + 1, (kk + 1) & 1);
            const int pb = kk & 1;
#pragma unroll
            for (int mi = 0; mi < 4; mi++)
#pragma unroll
                for (int ni = 0; ni < 8; ni++)
                    mma16816(acc[mi][ni], ra[pb][mi],
                             &rb[pb][ni >> 1][(ni & 1) * 2]);
        }
    }

#pragma unroll
    for (int mi = 0; mi < 4; mi++) {
#pragma unroll
        for (int ni = 0; ni < 8; ni++) {
            int row = bm + wm + mi * 16 + (lane >> 2);
            int col = bn + wn + ni * 8 + (lane & 3) * 2;
            *reinterpret_cast<float2*>(&y[(size_t)row * N_DIM + col]) =
                make_float2(acc[mi][ni][0], acc[mi][ni][1]);
            *reinterpret_cast<float2*>(&y[(size_t)(row + 8) * N_DIM + col]) =
                make_float2(acc[mi][ni][2], acc[mi][ni][3]);
        }
    }
}

// ---------------------------------------------------------------------------
extern "C" void kernel_launch(void* const* d_in, const int* in_sizes, int n_in,
                              void* d_out, int out_size) {
    const float* x  = (const float*)d_in[0];
    const int*   p  = (const int*)d_in[1];
    const float* cb = (const float*)d_in[2];
    float* y = (float*)d_out;

    split_x_kernel<<<(M_DIM * (size_t)K_DIM / 4) / 256, 256>>>(x);
    dequant_kernel<<<8192, 256>>>(p, cb);

    cudaFuncSetAttribute(gemm_kernel,
                         cudaFuncAttributeMaxDynamicSharedMemorySize, GEMM_SMEM);
    dim3 grid(M_DIM / BM, N_DIM / BN);   // 16 x 64 = 1024 tiles
    gemm_kernel<<<grid, GTHREADS, GEMM_SMEM>>>(y);
}

// round 5
// speedup vs baseline: 2.0067x; 1.0031x over previous
#include <cuda_runtime.h>
#include <cuda_fp16.h>
#include <stdint.h>

#define M_DIM 2048
#define N_DIM 8192
#define K_DIM 8192

__device__ __align__(128) __half g_A[(size_t)M_DIM * K_DIM];   // 33.5 MB
__device__ __align__(128) __half g_B[(size_t)N_DIM * K_DIM];   // 134 MB

#define FULL_TILES 888
#define TAIL_TILES 136
__device__ __align__(128) float g_part[(size_t)TAIL_TILES * 128 * 128]; // 8.9 MB

// ---------------------------------------------------------------------------
// Kernel 1: x (fp32) -> fp16   (2 float4 per thread for MLP)
// ---------------------------------------------------------------------------
__global__ void split_x_kernel(const float* __restrict__ x) {
    size_t i = ((size_t)blockIdx.x * blockDim.x + threadIdx.x) * 8;
    float4 v0 = *reinterpret_cast<const float4*>(x + i);
    float4 v1 = *reinterpret_cast<const float4*>(x + i + 4);
    __half2 h0 = __floats2half2_rn(v0.x, v0.y);
    __half2 h1 = __floats2half2_rn(v0.z, v0.w);
    __half2 h2 = __floats2half2_rn(v1.x, v1.y);
    __half2 h3 = __floats2half2_rn(v1.z, v1.w);
    uint4 out;
    out.x = *reinterpret_cast<uint32_t*>(&h0);
    out.y = *reinterpret_cast<uint32_t*>(&h1);
    out.z = *reinterpret_cast<uint32_t*>(&h2);
    out.w = *reinterpret_cast<uint32_t*>(&h3);
    *reinterpret_cast<uint4*>(&g_A[i]) = out;
}

// ---------------------------------------------------------------------------
// Kernel 2: dequant. 4 groups (32 weights) per thread.
// ---------------------------------------------------------------------------
__global__ void dequant_kernel(const int* __restrict__ p,
                               const float* __restrict__ cb) {
    int t = blockIdx.x * blockDim.x + threadIdx.x;      // 0 .. 2097151
    const int4* p4 = reinterpret_cast<const int4*>(p) + (size_t)t * 3;
    int4 pa = p4[0], pb = p4[1], pc = p4[2];
    int by[12] = {pa.x, pa.y, pa.z, pa.w, pb.x, pb.y, pb.z, pb.w,
                  pc.x, pc.y, pc.z, pc.w};

    const float4* c4 = reinterpret_cast<const float4*>(cb) + (size_t)(t >> 2) * 2;
    float4 f0 = __ldg(c4), f1 = __ldg(c4 + 1);
    uint64_t t0 = (uint64_t)__half_as_ushort(__float2half_rn(f0.x))
                | ((uint64_t)__half_as_ushort(__float2half_rn(f0.y)) << 16)
                | ((uint64_t)__half_as_ushort(__float2half_rn(f0.z)) << 32)
                | ((uint64_t)__half_as_ushort(__float2half_rn(f0.w)) << 48);
    uint64_t t1 = (uint64_t)__half_as_ushort(__float2half_rn(f1.x))
                | ((uint64_t)__half_as_ushort(__float2half_rn(f1.y)) << 16)
                | ((uint64_t)__half_as_ushort(__float2half_rn(f1.z)) << 32)
                | ((uint64_t)__half_as_ushort(__float2half_rn(f1.w)) << 48);

    uint4* dst = reinterpret_cast<uint4*>(g_B + (size_t)t * 32);
#pragma unroll
    for (int g = 0; g < 4; g++) {
        unsigned bits = (unsigned)by[3 * g] | ((unsigned)by[3 * g + 1] << 8)
                      | ((unsigned)by[3 * g + 2] << 16);
        uint32_t hv[8];
#pragma unroll
        for (int j = 0; j < 8; j++) {
            int idx = (bits >> (3 * j)) & 7;
            uint64_t tab = (idx & 4) ? t1 : t0;
            hv[j] = (uint32_t)(tab >> ((idx & 3) << 4)) & 0xFFFFu;
        }
        uint4 o;
        o.x = hv[0] | (hv[1] << 16);
        o.y = hv[2] | (hv[3] << 16);
        o.z = hv[4] | (hv[5] << 16);
        o.w = hv[6] | (hv[7] << 16);
        dst[g] = o;
    }
}

// ---------------------------------------------------------------------------
// Kernel 3: GEMM. BM=BN=128, BK=64, 4 warps, occ2, 3-stage cp.async.
// Tiles 0..887 full-K. Tiles 888..1023 split-K x2 (kz1 -> g_part).
// ---------------------------------------------------------------------------
#define BM 128
#define BN 128
#define BK 64
#define NSTAGE 3
#define A_BYTES (BM * BK * 2)
#define B_BYTES (BN * BK * 2)
#define STAGE_BYTES (A_BYTES + B_BYTES)
#define GEMM_SMEM (NSTAGE * STAGE_BYTES)
#define GTHREADS 128

__device__ __forceinline__ uint32_t smem_u32(const void* p) {
    uint32_t a;
    asm("{ .reg .u64 t; cvta.to.shared.u64 t, %1; cvt.u32.u64 %0, t; }"
        : "=r"(a) : "l"(p));
    return a;
}

__device__ __forceinline__ uint32_t swz(uint32_t base, int row, int chunk) {
    return base + row * 128 + (((chunk ^ row) & 7) << 4);
}

__device__ __forceinline__ void cp16(uint32_t dst, const void* src) {
    asm volatile("cp.async.cg.shared.global [%0], [%1], 16;\n"
                 :: "r"(dst), "l"(src));
}

__device__ __forceinline__ void ldsm4(uint32_t* r, uint32_t addr) {
    asm volatile("ldmatrix.sync.aligned.m8n8.x4.shared.b16 {%0,%1,%2,%3}, [%4];"
                 : "=r"(r[0]), "=r"(r[1]), "=r"(r[2]), "=r"(r[3]) : "r"(addr));
}

__device__ __forceinline__ void mma16816(float* c, const uint32_t* a,
                                         const uint32_t* b) {
    asm volatile(
        "mma.sync.aligned.m16n8k16.row.col.f32.f16.f16.f32 "
        "{%0,%1,%2,%3}, {%4,%5,%6,%7}, {%8,%9}, {%0,%1,%2,%3};\n"
        : "+f"(c[0]), "+f"(c[1]), "+f"(c[2]), "+f"(c[3])
        : "r"(a[0]), "r"(a[1]), "r"(a[2]), "r"(a[3]), "r"(b[0]), "r"(b[1]));
}

__device__ __forceinline__ void load_stage(uint32_t sb, int tid, int bm, int bn,
                                           int buf, int chunk) {
    const int k0 = chunk * BK;
    const uint32_t abase = sb + buf * STAGE_BYTES;
    const uint32_t bbase = abase + A_BYTES;
#pragma unroll
    for (int i = 0; i < 8; i++) {
        int c = tid + i * GTHREADS;
        int row = c >> 3, ch = c & 7;
        cp16(swz(abase, row, ch),
             g_A + (size_t)(bm + row) * K_DIM + k0 + ch * 8);
    }
#pragma unroll
    for (int i = 0; i < 8; i++) {
        int c = tid + i * GTHREADS;
        int row = c >> 3, ch = c & 7;
        cp16(swz(bbase, row, ch),
             g_B + (size_t)(bn + row) * K_DIM + k0 + ch * 8);
    }
    asm volatile("cp.async.commit_group;" ::: "memory");
}

__global__ void __launch_bounds__(GTHREADS, 2) gemm_kernel(float* __restrict__ y) {
    extern __shared__ char smem[];
    const uint32_t sb = smem_u32(smem);
    const int tid = threadIdx.x;
    const int w = tid >> 5, lane = tid & 31;
    const int wm = (w & 1) * 64;
    const int wn = (w >> 1) * 64;

    const int id = blockIdx.x;
    int tile, kz, iters;
    if (id < FULL_TILES) { tile = id; kz = 0; iters = 128; }
    else { int t = id - FULL_TILES; tile = FULL_TILES + (t >> 1); kz = t & 1; iters = 64; }
    const int kbase = kz * 64;
    const int bm = (tile & 15) * BM;
    const int bn = (tile >> 4) * BN;

    float acc[4][8][4];
#pragma unroll
    for (int i = 0; i < 4; i++)
#pragma unroll
        for (int j = 0; j < 8; j++)
#pragma unroll
            for (int r = 0; r < 4; r++) acc[i][j][r] = 0.0f;

#pragma unroll
    for (int s = 0; s < NSTAGE - 1; s++)
        load_stage(sb, tid, bm, bn, s, kbase + s);

    uint32_t ra[2][4][4], rb[2][4][4];

    auto ldfrag = [&](uint32_t abase, uint32_t bbase, int kk, int pb) {
#pragma unroll
        for (int mi = 0; mi < 4; mi++) {
            int row = wm + mi * 16 + (lane & 15);
            int ch = kk * 2 + (lane >> 4);
            ldsm4(ra[pb][mi], swz(abase, row, ch));
        }
#pragma unroll
        for (int np = 0; np < 4; np++) {
            int row = wn + np * 16 + (lane & 7) + ((lane >> 4) << 3);
            int ch = kk * 2 + ((lane >> 3) & 1);
            ldsm4(rb[pb][np], swz(bbase, row, ch));
        }
    };

    for (int it = 0; it < iters; it++) {
        if (it < iters - (NSTAGE - 1))
            asm volatile("cp.async.wait_group %0;" :: "n"(NSTAGE - 2) : "memory");
        else
            asm volatile("cp.async.wait_group 0;" ::: "memory");
        __syncthreads();

        const int j = it + NSTAGE - 1;
        if (j < iters) load_stage(sb, tid, bm, bn, j % NSTAGE, kbase + j);

        const int buf = it % NSTAGE;
        const uint32_t abase = sb + buf * STAGE_BYTES;
        const uint32_t bbase = abase + A_BYTES;

        ldfrag(abase, bbase, 0, 0);
#pragma unroll
        for (int kk = 0; kk < 4; kk++) {
            if (kk < 3) ldfrag(abase, bbase, kk + 1, (kk + 1) & 1);
            const int pb = kk & 1;
#pragma unroll
            for (int mi = 0; mi < 4; mi++)
#pragma unroll
                for (int ni = 0; ni < 8; ni++)
                    mma16816(acc[mi][ni], ra[pb][mi],
                             &rb[pb][ni >> 1][(ni & 1) * 2]);
        }
    }

    if (kz == 0) {
#pragma unroll
        for (int mi = 0; mi < 4; mi++) {
#pragma unroll
            for (int ni = 0; ni < 8; ni++) {
                int row = bm + wm + mi * 16 + (lane >> 2);
                int col = bn + wn + ni * 8 + (lane & 3) * 2;
                *reinterpret_cast<float2*>(&y[(size_t)row * N_DIM + col]) =
                    make_float2(acc[mi][ni][0], acc[mi][ni][1]);
                *reinterpret_cast<float2*>(&y[(size_t)(row + 8) * N_DIM + col]) =
                    make_float2(acc[mi][ni][2], acc[mi][ni][3]);
            }
        }
    } else {
        float* part = g_part + (size_t)(tile - FULL_TILES) * (BM * BN);
#pragma unroll
        for (int mi = 0; mi < 4; mi++) {
#pragma unroll
            for (int ni = 0; ni < 8; ni++) {
                int row = wm + mi * 16 + (lane >> 2);
                int col = wn + ni * 8 + (lane & 3) * 2;
                *reinterpret_cast<float2*>(&part[(size_t)row * BN + col]) =
                    make_float2(acc[mi][ni][0], acc[mi][ni][1]);
                *reinterpret_cast<float2*>(&part[(size_t)(row + 8) * BN + col]) =
                    make_float2(acc[mi][ni][2], acc[mi][ni][3]);
            }
        }
    }
}

// ---------------------------------------------------------------------------
// Kernel 4: combine partials for tail tiles.
// ---------------------------------------------------------------------------
__global__ void combine_kernel(float* __restrict__ y) {
    int idx = blockIdx.x * blockDim.x + threadIdx.x;    // 0 .. 557055
    int e = idx * 4;
    int s = e >> 14;                  // tail slot
    int rem = e & 16383;
    int r = rem >> 7, c = rem & 127;
    int tile = FULL_TILES + s;
    int row = (tile & 15) * BM + r;
    int col = (tile >> 4) * BN + c;
    float4 p = *reinterpret_cast<const float4*>(&g_part[(size_t)e]);
    float4* yp = reinterpret_cast<float4*>(&y[(size_t)row * N_DIM + col]);
    float4 v = *yp;
    v.x += p.x; v.y += p.y; v.z += p.z; v.w += p.w;
    *yp = v;
}

// ---------------------------------------------------------------------------
extern "C" void kernel_launch(void* const* d_in, const int* in_sizes, int n_in,
                              void* d_out, int out_size) {
    const float* x  = (const float*)d_in[0];
    const int*   p  = (const int*)d_in[1];
    const float* cb = (const float*)d_in[2];
    float* y = (float*)d_out;

    split_x_kernel<<<(M_DIM * (size_t)K_DIM / 8) / 256, 256>>>(x);
    dequant_kernel<<<8192, 256>>>(p, cb);

    cudaFuncSetAttribute(gemm_kernel,
                         cudaFuncAttributeMaxDynamicSharedMemorySize, GEMM_SMEM);
    gemm_kernel<<<FULL_TILES + 2 * TAIL_TILES, GTHREADS, GEMM_SMEM>>>(y);

    combine_kernel<<<2176, 256>>>(y);
}